// round 17
// baseline (speedup 1.0000x reference)
#include <cuda_runtime.h>
#include <cstdint>

// Problem constants (match reference)
#define NB     4
#define HH     512
#define WW     512
#define KK     4
#define FMAX   200000
#define SIGMA  1e-4f
#define GAMMA  1e-4f
#define EPSV   1e-10f
#define ZNEAR  1.0f
#define ZFAR   100.0f

#define NPIX (NB * HH * WW)   // 1,048,576 == 4096 * 256 exactly

// 1/SIGMA and 1/GAMMA are exactly representable (10000.0f) -> mul == div.
#define INV_SG 10000.0f

// Weight cutoff: exp((zi-zmax)*1e4) < e^-40 ~ 4e-18 is < 1e-10 relative to the
// dominant weight (>= ~1e-7); the fp32 reference itself underflows to 0 below
// e^-87. Skipping these fragments skips their gather entirely.
#define Z_CUT  (40.0f / INV_SG)   // 0.004

// smem layout (bytes) for the main kernel
#define S_PTF   0        // 4096  : 256 * int4
#define S_ZZ    4096     // 4096  : 256 * float4
#define S_DD    8192     // 4096  : 256 * float4
#define S_BARY  12288    // 12288 : 256 * 12 floats
#define S_OUT   24576    // 3072  : 256 * 3 floats
#define S_MBAR  27648    // 8     : mbarrier
#define SMEM_TOTAL 27712
#define TX_BYTES 24576u  // total bytes delivered by the 4 bulk loads

// Packed per-face record: 32 bytes = ONE 32B L2 sector, loaded with a single
// 256-bit LDG.  a = (n0x,n0y,n0z,n1x), b = (n1y,n1z,n2x,n2y); the 32 bits of
// n2z are hidden in the low 4 mantissa bits of the 8 stored floats (nibble i
// in component i). n2z decode is bit-exact; carriers perturbed <=15 ulp.
struct __align__(32) FaceRec { float4 a, b; };
__device__ FaceRec g_facerec[FMAX];

__device__ __forceinline__ unsigned fb(float v) { return __float_as_uint(v); }

__device__ __forceinline__ uint32_t smem_u32(const void* p) {
    uint32_t a;
    asm("{ .reg .u64 t; cvta.to.shared.u64 t, %1; cvt.u32.u64 %0, t; }"
        : "=r"(a) : "l"(p));
    return a;
}

// 256-bit global load (sm_100+): one instruction, one sector per lane.
__device__ __forceinline__ void ldg256(const FaceRec* p, float4& a, float4& b) {
    asm("ld.global.nc.v8.f32 {%0,%1,%2,%3,%4,%5,%6,%7}, [%8];"
        : "=f"(a.x), "=f"(a.y), "=f"(a.z), "=f"(a.w),
          "=f"(b.x), "=f"(b.y), "=f"(b.z), "=f"(b.w)
        : "l"(p));
}

__device__ __forceinline__ void bulk_g2s(uint32_t dst, const void* src,
                                         uint32_t bytes, uint32_t mbar) {
    asm volatile(
        "cp.async.bulk.shared::cta.global.mbarrier::complete_tx::bytes "
        "[%0], [%1], %2, [%3];"
        :: "r"(dst), "l"(src), "r"(bytes), "r"(mbar) : "memory");
}

__device__ __forceinline__ void mbar_wait_parity0(uint32_t mbar) {
    asm volatile(
        "{\n\t"
        ".reg .pred P1;\n\t"
        "WAIT_LOOP_%=:\n\t"
        "mbarrier.try_wait.parity.acquire.cta.shared::cta.b64 P1, [%0], 0, 0x989680;\n\t"
        "@P1 bra.uni WAIT_DONE_%=;\n\t"
        "bra.uni WAIT_LOOP_%=;\n\t"
        "WAIT_DONE_%=:\n\t"
        "}"
        :: "r"(mbar) : "memory");
}

// Gather of the 12B float3 at byte offset 12v with 1.5 loads/vertex average:
// one aligned float4 always; a predicated second float4 only when the normal
// crosses the 16B boundary. Bounds-safe for V=100000 (see R16 analysis).
__device__ __forceinline__ float3 load_vn(const float* __restrict__ vn, int v) {
    const unsigned B    = 12u * (unsigned)v;
    const unsigned q    = B >> 4;
    const unsigned rem4 = (B & 12u) >> 2;
    const float4 q0 = __ldg((const float4*)vn + q);
    float4 q1 = q0;
    if (rem4 >= 2)
        q1 = __ldg((const float4*)vn + q + 1);
    float3 r;
    r.x = (rem4 == 0) ? q0.x : (rem4 == 1) ? q0.y : (rem4 == 2) ? q0.z : q0.w;
    r.y = (rem4 == 0) ? q0.y : (rem4 == 1) ? q0.z : (rem4 == 2) ? q0.w : q1.x;
    r.z = (rem4 == 0) ? q0.z : (rem4 == 1) ? q0.w : (rem4 == 2) ? q1.x : q1.y;
    return r;
}

__global__ __launch_bounds__(256) void build_face_records(
    const float* __restrict__ vertex_normals,   // [V,3]
    const int*   __restrict__ faces,            // [F,3]
    int F)
{
    int f = blockIdx.x * blockDim.x + threadIdx.x;
    if (f >= F) return;
    const int v0 = __ldg(faces + 3 * f + 0);
    const int v1 = __ldg(faces + 3 * f + 1);
    const int v2 = __ldg(faces + 3 * f + 2);
    const float3 n0 = load_vn(vertex_normals, v0);
    const float3 n1 = load_vn(vertex_normals, v1);
    const float3 n2 = load_vn(vertex_normals, v2);

    float c[8] = {n0.x, n0.y, n0.z, n1.x, n1.y, n1.z, n2.x, n2.y};
    const unsigned u = __float_as_uint(n2.z);
    #pragma unroll
    for (int i = 0; i < 8; i++) {
        unsigned bits = (__float_as_uint(c[i]) & ~0xFu) | ((u >> (4 * i)) & 0xFu);
        c[i] = __uint_as_float(bits);
    }

    FaceRec r;
    r.a = make_float4(c[0], c[1], c[2], c[3]);
    r.b = make_float4(c[4], c[5], c[6], c[7]);
    g_facerec[f] = r;
}

__global__ __launch_bounds__(256) void normal_shader_kernel(
    const float* __restrict__ bary,             // [N,H,W,K,3]
    const float* __restrict__ dists,            // [N,H,W,K]
    const float* __restrict__ zbuf,             // [N,H,W,K]
    const int*   __restrict__ pix_to_face,      // [N,H,W,K]
    float*       __restrict__ out)              // [N,H,W,3]
{
    extern __shared__ char smem[];
    const int tid = threadIdx.x;
    const int bid = blockIdx.x;                 // grid covers NPIX exactly
    const uint32_t sb = smem_u32(smem);

    // ---- TMA bulk prefetch of the CTA's contiguous input blocks ----
    if (tid == 0) {
        asm volatile("mbarrier.init.shared.b64 [%0], %1;"
                     :: "r"(sb + S_MBAR), "r"(1u) : "memory");
    }
    __syncthreads();
    if (tid == 0) {
        asm volatile("mbarrier.arrive.expect_tx.shared.b64 _, [%0], %1;"
                     :: "r"(sb + S_MBAR), "r"(TX_BYTES) : "memory");
        bulk_g2s(sb + S_PTF,  pix_to_face + (size_t)bid * 1024, 4096u,  sb + S_MBAR);
        bulk_g2s(sb + S_ZZ,   zbuf        + (size_t)bid * 1024, 4096u,  sb + S_MBAR);
        bulk_g2s(sb + S_DD,   dists       + (size_t)bid * 1024, 4096u,  sb + S_MBAR);
        bulk_g2s(sb + S_BARY, bary        + (size_t)bid * 3072, 12288u, sb + S_MBAR);
    }
    mbar_wait_parity0(sb + S_MBAR);

    // ---- per-pixel data now in smem (LDS, conflict-light) ----
    const int4   ptf = ((const int4*)(smem + S_PTF))[tid];
    const float4 zz  = ((const float4*)(smem + S_ZZ))[tid];
    const float4 dd  = ((const float4*)(smem + S_DD))[tid];
    const float4* bb = (const float4*)(smem + S_BARY) + tid * 3;
    const float4 b0 = bb[0];
    const float4 b1 = bb[1];
    const float4 b2 = bb[2];

    const int   face[KK] = {ptf.x, ptf.y, ptf.z, ptf.w};
    const float zk[KK]   = {zz.x, zz.y, zz.z, zz.w};
    const float dk[KK]   = {dd.x, dd.y, dd.z, dd.w};
    const float bw[KK][3] = {
        {b0.x, b0.y, b0.z},
        {b0.w, b1.x, b1.y},
        {b1.z, b1.w, b2.x},
        {b2.y, b2.z, b2.w}
    };

    // zi MUST use exact IEEE div: 1 ulp amplifies ~1e4x in the exponent.
    float zinv[KK];
    float zmax = EPSV;
    #pragma unroll
    for (int k = 0; k < KK; k++) {
        const float zi = (face[k] >= 0) ? ((ZFAR - zk[k]) / (ZFAR - ZNEAR)) : 0.f;
        zinv[k] = zi;
        zmax = fmaxf(zmax, zi);
    }
    const float thr = zmax - Z_CUT;

    // ---- gather + blend ONLY fragments whose softmax weight is nonzero ----
    // (expected ~1.05 of 4 — GAMMA=1e-4 makes this a near-argmax; all other
    //  weights underflow to 0 in fp32, in the reference as well)
    float accx = 0.f, accy = 0.f, accz = 0.f, wsum = 0.f;
    #pragma unroll
    for (int k = 0; k < KK; k++) {
        if (face[k] >= 0 && zinv[k] > thr) {
            float4 a, b;
            ldg256(g_facerec + face[k], a, b);
            // reconstruct n2z from the 8 stolen nibbles (bit-exact)
            unsigned u =  (fb(a.x) & 0xFu)
                       | ((fb(a.y) & 0xFu) << 4)
                       | ((fb(a.z) & 0xFu) << 8)
                       | ((fb(a.w) & 0xFu) << 12)
                       | ((fb(b.x) & 0xFu) << 16)
                       | ((fb(b.y) & 0xFu) << 20)
                       | ((fb(b.z) & 0xFu) << 24)
                       | ((fb(b.w) & 0xFu) << 28);
            const float n2z = __uint_as_float(u);
            const float w0 = bw[k][0], w1 = bw[k][1], w2 = bw[k][2];
            // prob = sigmoid(-d/SIGMA)  (arg ~N(0,1); __expf err ~1e-6)
            const float pr = __fdividef(1.0f, 1.0f + __expf(dk[k] * INV_SG));
            const float w  = pr * __expf((zinv[k] - zmax) * INV_SG);
            wsum += w;
            accx += w * (w0 * a.x + w1 * a.w + w2 * b.z);
            accy += w * (w0 * a.y + w1 * b.x + w2 * b.w);
            accz += w * (w0 * a.z + w1 * b.y + w2 * n2z);
        }
    }

    const float delta  = fmaxf(__expf((EPSV - zmax) * INV_SG), EPSV);
    const float rdenom = __fdividef(1.0f, wsum + delta);

    // bg = (1,1,1)
    float rx = (accx + delta) * rdenom;
    float ry = (accy + delta) * rdenom;
    float rz = (accz + delta) * rdenom;

    const float n2 = rx * rx + ry * ry + rz * rz;
    const float inv = (n2 > 1e-24f) ? rsqrtf(n2) : 1e12f;
    rx *= inv; ry *= inv; rz *= inv;

    // ---- stage output in smem, emit with ONE bulk store ----
    float* so = (float*)(smem + S_OUT);
    so[3 * tid + 0] = rx;
    so[3 * tid + 1] = ry;
    so[3 * tid + 2] = rz;
    __syncthreads();
    if (tid == 0) {
        asm volatile("fence.proxy.async.shared::cta;" ::: "memory");
        asm volatile("cp.async.bulk.global.shared::cta.bulk_group [%0], [%1], %2;"
                     :: "l"(out + (size_t)bid * 768), "r"(sb + S_OUT), "r"(3072u)
                     : "memory");
        asm volatile("cp.async.bulk.commit_group;" ::: "memory");
        asm volatile("cp.async.bulk.wait_group 0;" ::: "memory");
    }
}

extern "C" void kernel_launch(void* const* d_in, const int* in_sizes, int n_in,
                              void* d_out, int out_size)
{
    // metadata order: verts, vertex_normals, bary_coords, dists, zbuf, faces, pix_to_face
    const float* vertex_normals = (const float*)d_in[1];
    const float* bary           = (const float*)d_in[2];
    const float* dists          = (const float*)d_in[3];
    const float* zbuf           = (const float*)d_in[4];
    const int*   faces          = (const int*)d_in[5];
    const int*   pix_to_face    = (const int*)d_in[6];
    float*       out            = (float*)d_out;

    const int F = in_sizes[5] / 3;   // 200000
    const int threads = 256;

    build_face_records<<<(F + threads - 1) / threads, threads>>>(
        vertex_normals, faces, F);

    normal_shader_kernel<<<NPIX / threads, threads, SMEM_TOTAL>>>(
        bary, dists, zbuf, pix_to_face, out);
}